// round 5
// baseline (speedup 1.0000x reference)
#include <cuda_runtime.h>

#define D 64
#define MAXN 50000
#define MAXE 800000
#define SCAN_B 1024
#define NB_MAX ((MAXN + SCAN_B - 1) / SCAN_B)

// ---------------- device scratch (no allocation allowed) ----------------
__device__ float g_h[MAXN * D];
__device__ float g_a[MAXN * D];
__device__ float g_as[MAXN];
__device__ float g_ad[MAXN];
__device__ int   g_deg[MAXN];
__device__ int   g_cur[MAXN];
__device__ int   g_offs[MAXN + 1];
__device__ int   g_bsums[NB_MAX];
__device__ int   g_csr[MAXE];
__device__ int   g_is64;

__device__ __forceinline__ float lrelu(float x, float s) { return x > 0.f ? x : s * x; }

__device__ __forceinline__ int edge_val(const void* eidx, int idx, int is64) {
    return is64 ? (int)((const long long*)eidx)[idx] : ((const int*)eidx)[idx];
}

// ---------------- init: zero counters + edge dtype detection ----------------
__global__ void init_kernel(const void* eidx, int n) {
    int i = blockIdx.x * blockDim.x + threadIdx.x;
    if (i < n) { g_deg[i] = 0; g_cur[i] = 0; }
    if (i == 0) {
        const long long* p = (const long long*)eidx;
        int ok = 1;
        #pragma unroll
        for (int k = 0; k < 32; k++) {
            long long v = p[k];
            if (v < 0 || v >= (long long)n) { ok = 0; break; }
        }
        g_is64 = ok;
    }
}

__global__ void hist_kernel(const void* eidx, int e) {
    int i = blockIdx.x * blockDim.x + threadIdx.x;
    if (i < e) {
        int d = edge_val(eidx, e + i, g_is64);
        atomicAdd(&g_deg[d], 1);
    }
}

__global__ void scan_block_kernel(int n) {
    __shared__ int wsum[32];
    int t = threadIdx.x, lane = t & 31, wid = t >> 5;
    int gid = blockIdx.x * SCAN_B + t;
    int v = (gid < n) ? g_deg[gid] : 0;
    int x = v;
    #pragma unroll
    for (int o = 1; o < 32; o <<= 1) {
        int y = __shfl_up_sync(0xffffffffu, x, o);
        if (lane >= o) x += y;
    }
    if (lane == 31) wsum[wid] = x;
    __syncthreads();
    if (wid == 0) {
        int s = wsum[lane];
        #pragma unroll
        for (int o = 1; o < 32; o <<= 1) {
            int y = __shfl_up_sync(0xffffffffu, s, o);
            if (lane >= o) s += y;
        }
        wsum[lane] = s;
    }
    __syncthreads();
    int incl = x + (wid > 0 ? wsum[wid - 1] : 0);
    if (gid < n) g_offs[gid] = incl - v;
    if (t == SCAN_B - 1) g_bsums[blockIdx.x] = incl;
}

__global__ void scan_fixup_kernel(int n, int e, int nb) {
    __shared__ int s_pre;
    int t = threadIdx.x, b = blockIdx.x;
    if (t < 32) {
        int p = 0;
        for (int i = t; i < b; i += 32) p += g_bsums[i];
        #pragma unroll
        for (int o = 16; o >= 1; o >>= 1)
            p += __shfl_xor_sync(0xffffffffu, p, o);
        if (t == 0) s_pre = p;
    }
    __syncthreads();
    int pre = s_pre;
    int gid = b * SCAN_B + t;
    if (gid < n) g_offs[gid] += pre;
    if (gid == 0) g_offs[n] = e;
}

__global__ void scatter_kernel(const void* eidx, int e) {
    int i = blockIdx.x * blockDim.x + threadIdx.x;
    if (i < e) {
        int is64 = g_is64;
        int d = edge_val(eidx, e + i, is64);
        int s = edge_val(eidx, i, is64);
        int pos = g_offs[d] + atomicAdd(&g_cur[d], 1);
        g_csr[pos] = s;
    }
}

// ---------------- GEMM: H = X @ W^T ----------------
// 256 threads, 64 rows/block, 4 rows x 4 cols per thread.
// X kept NATURAL [r][k] in smem (coalesced stage, broadcast reads).
// as/ad via rank-1 identity: as = X @ (W^T a_src) — no shuffles at all.
#define PITCH 68
__global__ void __launch_bounds__(256) gemm_kernel(
        const float* __restrict__ X, const float* __restrict__ W,
        const float* __restrict__ a_src, const float* __restrict__ a_dst, int n) {
    __shared__ __align__(16) float sWt[D * PITCH];   // sWt[k*PITCH + c] = W[c][k]
    __shared__ __align__(16) float sX[64 * PITCH];   // natural: sX[r*PITCH + k]
    __shared__ __align__(16) float s_was[D], s_wad[D];
    int t = threadIdx.x;
    int base = blockIdx.x * 64;

    // stage W transposed (coalesced LDG, conflict-free scatter STS)
    {
        const float4* Wv = (const float4*)W;
        for (int idx = t; idx < D * (D / 4); idx += 256) {
            int c = idx >> 4, k0 = (idx & 15) << 2;
            float4 w = Wv[idx];
            sWt[(k0    ) * PITCH + c] = w.x;
            sWt[(k0 + 1) * PITCH + c] = w.y;
            sWt[(k0 + 2) * PITCH + c] = w.z;
            sWt[(k0 + 3) * PITCH + c] = w.w;
        }
    }
    // stage X natural (coalesced LDG float4 -> STS.128)
    {
        const float4* Xv = (const float4*)X;
        #pragma unroll
        for (int idx = t; idx < 64 * 16; idx += 256) {
            int r = idx >> 4, q = idx & 15;
            int gr = base + r;
            float4 v = make_float4(0.f, 0.f, 0.f, 0.f);
            if (gr < n) v = Xv[gr * 16 + q];
            *reinterpret_cast<float4*>(&sX[r * PITCH + q * 4]) = v;
        }
    }
    __syncthreads();

    // w_as[k] = sum_c W[c][k] a_src[c]; w_ad likewise (threads 0..63)
    if (t < D) {
        float was = 0.f, wad = 0.f;
        const float4* av = (const float4*)a_src;
        const float4* dv = (const float4*)a_dst;
        #pragma unroll
        for (int q = 0; q < 16; q++) {
            float4 wv = *reinterpret_cast<const float4*>(&sWt[t * PITCH + q * 4]);
            float4 a = av[q], d = dv[q];
            was += wv.x * a.x + wv.y * a.y + wv.z * a.z + wv.w * a.w;
            wad += wv.x * d.x + wv.y * d.y + wv.z * d.z + wv.w * d.w;
        }
        s_was[t] = was; s_wad[t] = wad;
    }
    __syncthreads();

    // as/ad per row (threads 0..63), straight from natural sX — no shuffles
    if (t < 64) {
        int gr = base + t;
        if (gr < n) {
            float asp = 0.f, adp = 0.f;
            #pragma unroll
            for (int q = 0; q < 16; q++) {
                float4 xv = *reinterpret_cast<const float4*>(&sX[t * PITCH + q * 4]);
                float4 wa = *reinterpret_cast<const float4*>(&s_was[q * 4]);
                float4 wd = *reinterpret_cast<const float4*>(&s_wad[q * 4]);
                asp += xv.x * wa.x + xv.y * wa.y + xv.z * wa.z + xv.w * wa.w;
                adp += xv.x * wd.x + xv.y * wd.y + xv.z * wd.z + xv.w * wd.w;
            }
            g_as[gr] = asp; g_ad[gr] = adp;
        }
    }

    // mainloop: 4 rows x 4 cols per thread
    int r0 = (t >> 4) << 2;     // rows r0..r0+3
    int c0 = (t & 15) << 2;     // cols c0..c0+3
    float acc[4][4];
    #pragma unroll
    for (int i = 0; i < 4; i++)
        #pragma unroll
        for (int j = 0; j < 4; j++) acc[i][j] = 0.f;

    const float* x0p = &sX[(r0    ) * PITCH];
    const float* x1p = &sX[(r0 + 1) * PITCH];
    const float* x2p = &sX[(r0 + 2) * PITCH];
    const float* x3p = &sX[(r0 + 3) * PITCH];

    #pragma unroll 4
    for (int k0 = 0; k0 < D; k0 += 4) {
        // 4 x-row float4s (half-warp broadcasts) + 4 w float4s per 4k -> 64 FFMA
        float4 xa = *reinterpret_cast<const float4*>(&x0p[k0]);
        float4 xb = *reinterpret_cast<const float4*>(&x1p[k0]);
        float4 xc = *reinterpret_cast<const float4*>(&x2p[k0]);
        float4 xd = *reinterpret_cast<const float4*>(&x3p[k0]);
        #pragma unroll
        for (int j = 0; j < 4; j++) {
            float4 wv = *reinterpret_cast<const float4*>(&sWt[(k0 + j) * PITCH + c0]);
            float xs0 = j == 0 ? xa.x : j == 1 ? xa.y : j == 2 ? xa.z : xa.w;
            float xs1 = j == 0 ? xb.x : j == 1 ? xb.y : j == 2 ? xb.z : xb.w;
            float xs2 = j == 0 ? xc.x : j == 1 ? xc.y : j == 2 ? xc.z : xc.w;
            float xs3 = j == 0 ? xd.x : j == 1 ? xd.y : j == 2 ? xd.z : xd.w;
            acc[0][0] += xs0 * wv.x; acc[0][1] += xs0 * wv.y; acc[0][2] += xs0 * wv.z; acc[0][3] += xs0 * wv.w;
            acc[1][0] += xs1 * wv.x; acc[1][1] += xs1 * wv.y; acc[1][2] += xs1 * wv.z; acc[1][3] += xs1 * wv.w;
            acc[2][0] += xs2 * wv.x; acc[2][1] += xs2 * wv.y; acc[2][2] += xs2 * wv.z; acc[2][3] += xs2 * wv.w;
            acc[3][0] += xs3 * wv.x; acc[3][1] += xs3 * wv.y; acc[3][2] += xs3 * wv.z; acc[3][3] += xs3 * wv.w;
        }
    }

    #pragma unroll
    for (int i = 0; i < 4; i++) {
        int gr = base + r0 + i;
        if (gr < n) {
            float4 v; v.x = acc[i][0]; v.y = acc[i][1]; v.z = acc[i][2]; v.w = acc[i][3];
            *reinterpret_cast<float4*>(&g_h[gr * D + c0]) = v;
        }
    }
}

// ---------------- per-dst softmax aggregation: 1 warp / node, single pass ----
__global__ void agg_kernel(const float* __restrict__ b, int n, int last,
                           const float* __restrict__ Wout,
                           const float* __restrict__ bout,
                           float* __restrict__ out) {
    int v = (blockIdx.x * blockDim.x + threadIdx.x) >> 5;
    int lane = threadIdx.x & 31;
    if (v >= n) return;

    int beg = g_offs[v], end = g_offs[v + 1];
    float adv = g_ad[v];
    int c0 = lane * 2;

    float w0 = __expf(lrelu(g_as[v] + adv, 0.2f));
    float denom = w0;
    float2 hs = *reinterpret_cast<const float2*>(&g_h[v * D + c0]);
    float a0 = w0 * hs.x, a1 = w0 * hs.y;

    int i = beg;
    for (; i + 4 <= end; i += 4) {
        int s0 = g_csr[i];
        int s1 = g_csr[i + 1];
        int s2 = g_csr[i + 2];
        int s3 = g_csr[i + 3];
        float as0 = g_as[s0], as1 = g_as[s1], as2 = g_as[s2], as3 = g_as[s3];
        float2 h0 = *reinterpret_cast<const float2*>(&g_h[s0 * D + c0]);
        float2 h1 = *reinterpret_cast<const float2*>(&g_h[s1 * D + c0]);
        float2 h2 = *reinterpret_cast<const float2*>(&g_h[s2 * D + c0]);
        float2 h3 = *reinterpret_cast<const float2*>(&g_h[s3 * D + c0]);
        float e0 = __expf(lrelu(as0 + adv, 0.2f));
        float e1 = __expf(lrelu(as1 + adv, 0.2f));
        float e2 = __expf(lrelu(as2 + adv, 0.2f));
        float e3 = __expf(lrelu(as3 + adv, 0.2f));
        denom += (e0 + e1) + (e2 + e3);
        a0 += e0 * h0.x + e1 * h1.x + e2 * h2.x + e3 * h3.x;
        a1 += e0 * h0.y + e1 * h1.y + e2 * h2.y + e3 * h3.y;
    }
    for (; i < end; i++) {
        int s0 = g_csr[i];
        float e0 = __expf(lrelu(g_as[s0] + adv, 0.2f));
        float2 h0 = *reinterpret_cast<const float2*>(&g_h[s0 * D + c0]);
        denom += e0; a0 += e0 * h0.x; a1 += e0 * h0.y;
    }

    float inv = 1.0f / denom;
    float o0 = lrelu(a0 * inv + b[c0],     0.01f);
    float o1 = lrelu(a1 * inv + b[c0 + 1], 0.01f);
    if (!last) {
        float2 r; r.x = o0; r.y = o1;
        *reinterpret_cast<float2*>(&g_a[v * D + c0]) = r;
    } else {
        float s = o0 * Wout[c0] + o1 * Wout[c0 + 1];
        #pragma unroll
        for (int o = 16; o >= 1; o >>= 1)
            s += __shfl_xor_sync(0xffffffffu, s, o);
        if (lane == 0) out[v] = s + bout[0];
    }
}

// ---------------- launch ----------------
extern "C" void kernel_launch(void* const* d_in, const int* in_sizes, int n_in,
                              void* d_out, int out_size) {
    const float* x = (const float*)d_in[0];
    const float* W[3]    = {(const float*)d_in[1], (const float*)d_in[5], (const float*)d_in[9]};
    const float* asrc[3] = {(const float*)d_in[2], (const float*)d_in[6], (const float*)d_in[10]};
    const float* adst[3] = {(const float*)d_in[3], (const float*)d_in[7], (const float*)d_in[11]};
    const float* bias[3] = {(const float*)d_in[4], (const float*)d_in[8], (const float*)d_in[12]};
    const float* Wout = (const float*)d_in[13];
    const float* bout = (const float*)d_in[14];
    const void*  eidx = d_in[15];

    int n = in_sizes[0] / D;
    int e = in_sizes[15] / 2;

    void* a_ptr = nullptr;
    cudaGetSymbolAddress(&a_ptr, g_a);
    const float* abuf = (const float*)a_ptr;

    int nb = (n + SCAN_B - 1) / SCAN_B;
    int eb = (e + 255) / 256;
    int zb = (n + 255) / 256;
    int gemm_b = (n + 63) / 64;
    int agg_b  = (n * 32 + 255) / 256;

    init_kernel<<<zb, 256>>>(eidx, n);                             // 1
    hist_kernel<<<eb, 256>>>(eidx, e);                             // 2
    scan_block_kernel<<<nb, SCAN_B>>>(n);                          // 3
    gemm_kernel<<<gemm_b, 256>>>(x, W[0], asrc[0], adst[0], n);    // 4  <- profiled slot
    scan_fixup_kernel<<<nb, SCAN_B>>>(n, e, nb);                   // 5
    scatter_kernel<<<eb, 256>>>(eidx, e);                          // 6
    agg_kernel<<<agg_b, 256>>>(bias[0], n, 0, Wout, bout, (float*)d_out);   // 7

    for (int l = 1; l < 3; l++) {
        gemm_kernel<<<gemm_b, 256>>>(abuf, W[l], asrc[l], adst[l], n);
        agg_kernel<<<agg_b, 256>>>(bias[l], n, (l == 2) ? 1 : 0,
                                   Wout, bout, (float*)d_out);
    }
}

// round 6
// speedup vs baseline: 1.1254x; 1.1254x over previous
#include <cuda_runtime.h>

#define D 64
#define MAXN 50000
#define MAXE 800000
#define SCAN_B 1024
#define NB_MAX ((MAXN + SCAN_B - 1) / SCAN_B)

// ---------------- device scratch (no allocation allowed) ----------------
__device__ float g_h[MAXN * D];
__device__ float g_a[MAXN * D];
__device__ float g_as[MAXN];
__device__ float g_ad[MAXN];
__device__ int   g_deg[MAXN];
__device__ int   g_cur[MAXN];
__device__ int   g_offs[MAXN + 1];
__device__ int   g_bsums[NB_MAX];
__device__ int   g_csr[MAXE];
__device__ int   g_is64;

__device__ __forceinline__ float lrelu(float x, float s) { return x > 0.f ? x : s * x; }

__device__ __forceinline__ int edge_val(const void* eidx, int idx, int is64) {
    return is64 ? (int)((const long long*)eidx)[idx] : ((const int*)eidx)[idx];
}

// ---------------- init / CSR build (unchanged) ----------------
__global__ void init_kernel(const void* eidx, int n) {
    int i = blockIdx.x * blockDim.x + threadIdx.x;
    if (i < n) { g_deg[i] = 0; g_cur[i] = 0; }
    if (i == 0) {
        const long long* p = (const long long*)eidx;
        int ok = 1;
        #pragma unroll
        for (int k = 0; k < 32; k++) {
            long long v = p[k];
            if (v < 0 || v >= (long long)n) { ok = 0; break; }
        }
        g_is64 = ok;
    }
}

__global__ void hist_kernel(const void* eidx, int e) {
    int i = blockIdx.x * blockDim.x + threadIdx.x;
    if (i < e) {
        int d = edge_val(eidx, e + i, g_is64);
        atomicAdd(&g_deg[d], 1);
    }
}

__global__ void scan_block_kernel(int n) {
    __shared__ int wsum[32];
    int t = threadIdx.x, lane = t & 31, wid = t >> 5;
    int gid = blockIdx.x * SCAN_B + t;
    int v = (gid < n) ? g_deg[gid] : 0;
    int x = v;
    #pragma unroll
    for (int o = 1; o < 32; o <<= 1) {
        int y = __shfl_up_sync(0xffffffffu, x, o);
        if (lane >= o) x += y;
    }
    if (lane == 31) wsum[wid] = x;
    __syncthreads();
    if (wid == 0) {
        int s = wsum[lane];
        #pragma unroll
        for (int o = 1; o < 32; o <<= 1) {
            int y = __shfl_up_sync(0xffffffffu, s, o);
            if (lane >= o) s += y;
        }
        wsum[lane] = s;
    }
    __syncthreads();
    int incl = x + (wid > 0 ? wsum[wid - 1] : 0);
    if (gid < n) g_offs[gid] = incl - v;
    if (t == SCAN_B - 1) g_bsums[blockIdx.x] = incl;
}

__global__ void scan_fixup_kernel(int n, int e, int nb) {
    __shared__ int s_pre;
    int t = threadIdx.x, b = blockIdx.x;
    if (t < 32) {
        int p = 0;
        for (int i = t; i < b; i += 32) p += g_bsums[i];
        #pragma unroll
        for (int o = 16; o >= 1; o >>= 1)
            p += __shfl_xor_sync(0xffffffffu, p, o);
        if (t == 0) s_pre = p;
    }
    __syncthreads();
    int pre = s_pre;
    int gid = b * SCAN_B + t;
    if (gid < n) g_offs[gid] += pre;
    if (gid == 0) g_offs[n] = e;
}

__global__ void scatter_kernel(const void* eidx, int e) {
    int i = blockIdx.x * blockDim.x + threadIdx.x;
    if (i < e) {
        int is64 = g_is64;
        int d = edge_val(eidx, e + i, is64);
        int s = edge_val(eidx, i, is64);
        int pos = g_offs[d] + atomicAdd(&g_cur[d], 1);
        g_csr[pos] = s;
    }
}

// ---------------- GEMM: H = X @ W^T, 128 rows/block, 8x4 per thread ------
// sXt transposed [k][r] (pitch 128, conflict-free), sWt transposed [k][c]
// (pitch 68). Per k-step: 3x LDS.128 feed 32 FFMA.
// as/ad via rank-1: w_as = W^T a_src in smem, then rows dot w_as. No shuffles.
#define XP 128             // sXt pitch (rows)
#define WP 68              // sWt pitch (cols)
#define SX_F (D * XP)      // 8192 floats
#define SW_F (D * WP)      // 4352 floats
#define GEMM_SMEM ((SX_F + SW_F + 2 * D) * 4)   // 50688 bytes

__global__ void __launch_bounds__(256) gemm_kernel(
        const float* __restrict__ X, const float* __restrict__ W,
        const float* __restrict__ a_src, const float* __restrict__ a_dst, int n) {
    extern __shared__ __align__(16) float sm[];
    float* sXt   = sm;                 // [k*XP + r]
    float* sWt   = sm + SX_F;          // [k*WP + c]
    float* s_was = sm + SX_F + SW_F;   // [D]
    float* s_wad = s_was + D;

    int t = threadIdx.x;
    int base = blockIdx.x * 128;

    // stage W transposed: thread owns col c=t&63, k-chunk half=t>>6 (16 k each)
    {
        int c = t & 63, kh = (t >> 6) << 4;   // kh: 16 k values
        const float4* Wr = (const float4*)(W + c * D);
        #pragma unroll
        for (int q = 0; q < 4; q++) {
            int k0 = kh + q * 4;
            float4 w = Wr[k0 >> 2];
            sWt[(k0    ) * WP + c] = w.x;
            sWt[(k0 + 1) * WP + c] = w.y;
            sWt[(k0 + 2) * WP + c] = w.z;
            sWt[(k0 + 3) * WP + c] = w.w;
        }
    }
    // stage X transposed: thread owns row r=t&127, col-half=t>>7 (32 cols)
    {
        int r = t & 127, ch = (t >> 7) << 5;
        int gr = base + r;
        const float4* Xv = (const float4*)X;
        #pragma unroll
        for (int q = 0; q < 8; q++) {
            int c0 = ch + q * 4;
            float4 v = make_float4(0.f, 0.f, 0.f, 0.f);
            if (gr < n) v = Xv[gr * 16 + (c0 >> 2)];
            sXt[(c0    ) * XP + r] = v.x;
            sXt[(c0 + 1) * XP + r] = v.y;
            sXt[(c0 + 2) * XP + r] = v.z;
            sXt[(c0 + 3) * XP + r] = v.w;
        }
    }
    __syncthreads();

    // w_as[k] = sum_c W[c][k] a_src[c] (threads 0..63)
    if (t < D) {
        float was = 0.f, wad = 0.f;
        const float4* av = (const float4*)a_src;
        const float4* dv = (const float4*)a_dst;
        #pragma unroll
        for (int q = 0; q < 16; q++) {
            float4 wv = *reinterpret_cast<const float4*>(&sWt[t * WP + q * 4]);
            float4 a = av[q], dd = dv[q];
            was += wv.x * a.x + wv.y * a.y + wv.z * a.z + wv.w * a.w;
            wad += wv.x * dd.x + wv.y * dd.y + wv.z * dd.z + wv.w * dd.w;
        }
        s_was[t] = was; s_wad[t] = wad;
    }
    __syncthreads();

    // as/ad per row (threads 0..127): column reads of sXt, conflict-free
    if (t < 128) {
        int gr = base + t;
        if (gr < n) {
            float asp = 0.f, adp = 0.f;
            #pragma unroll 8
            for (int k = 0; k < D; k++) {
                float xv = sXt[k * XP + t];
                asp += xv * s_was[k];
                adp += xv * s_wad[k];
            }
            g_as[gr] = asp; g_ad[gr] = adp;
        }
    }

    // mainloop: 8 rows x 4 cols per thread
    int r0 = (t >> 4) << 3;     // rows r0..r0+7
    int c0 = (t & 15) << 2;     // cols c0..c0+3
    float acc[8][4];
    #pragma unroll
    for (int i = 0; i < 8; i++)
        #pragma unroll
        for (int j = 0; j < 4; j++) acc[i][j] = 0.f;

    #pragma unroll 4
    for (int k = 0; k < D; k++) {
        float4 xlo = *reinterpret_cast<const float4*>(&sXt[k * XP + r0]);
        float4 xhi = *reinterpret_cast<const float4*>(&sXt[k * XP + r0 + 4]);
        float4 wv  = *reinterpret_cast<const float4*>(&sWt[k * WP + c0]);
        acc[0][0] += xlo.x * wv.x; acc[0][1] += xlo.x * wv.y; acc[0][2] += xlo.x * wv.z; acc[0][3] += xlo.x * wv.w;
        acc[1][0] += xlo.y * wv.x; acc[1][1] += xlo.y * wv.y; acc[1][2] += xlo.y * wv.z; acc[1][3] += xlo.y * wv.w;
        acc[2][0] += xlo.z * wv.x; acc[2][1] += xlo.z * wv.y; acc[2][2] += xlo.z * wv.z; acc[2][3] += xlo.z * wv.w;
        acc[3][0] += xlo.w * wv.x; acc[3][1] += xlo.w * wv.y; acc[3][2] += xlo.w * wv.z; acc[3][3] += xlo.w * wv.w;
        acc[4][0] += xhi.x * wv.x; acc[4][1] += xhi.x * wv.y; acc[4][2] += xhi.x * wv.z; acc[4][3] += xhi.x * wv.w;
        acc[5][0] += xhi.y * wv.x; acc[5][1] += xhi.y * wv.y; acc[5][2] += xhi.y * wv.z; acc[5][3] += xhi.y * wv.w;
        acc[6][0] += xhi.z * wv.x; acc[6][1] += xhi.z * wv.y; acc[6][2] += xhi.z * wv.z; acc[6][3] += xhi.z * wv.w;
        acc[7][0] += xhi.w * wv.x; acc[7][1] += xhi.w * wv.y; acc[7][2] += xhi.w * wv.z; acc[7][3] += xhi.w * wv.w;
    }

    #pragma unroll
    for (int i = 0; i < 8; i++) {
        int gr = base + r0 + i;
        if (gr < n) {
            float4 v; v.x = acc[i][0]; v.y = acc[i][1]; v.z = acc[i][2]; v.w = acc[i][3];
            *reinterpret_cast<float4*>(&g_h[gr * D + c0]) = v;
        }
    }
}

// ---------------- aggregation: 4 nodes per warp, 8 lanes per node ----------
// lane sl owns cols sl*4 and sl*4+32 -> each warp gather inst = 1 full 128B
// line per node. One exp warp-inst serves 4 edges (4 nodes).
__global__ void agg_kernel(const float* __restrict__ b, int n, int last,
                           const float* __restrict__ Wout,
                           const float* __restrict__ bout,
                           float* __restrict__ out) {
    int wid_g = (blockIdx.x * blockDim.x + threadIdx.x) >> 5;
    int lane = threadIdx.x & 31;
    if (wid_g * 4 >= n) return;
    int sub = lane >> 3, sl = lane & 7;
    int v = wid_g * 4 + sub;
    bool valid = v < n;
    int vc = valid ? v : (n - 1);

    int beg = g_offs[vc];
    int deg = valid ? (g_offs[vc + 1] - beg) : 0;
    float adv = g_ad[vc];
    int ca = sl * 4, cb = ca + 32;

    // self-loop
    float w0 = valid ? __expf(lrelu(g_as[vc] + adv, 0.2f)) : 0.f;
    float denom = w0;
    float4 ha = *reinterpret_cast<const float4*>(&g_h[vc * D + ca]);
    float4 hb = *reinterpret_cast<const float4*>(&g_h[vc * D + cb]);
    float4 A; A.x = w0 * ha.x; A.y = w0 * ha.y; A.z = w0 * ha.z; A.w = w0 * ha.w;
    float4 B; B.x = w0 * hb.x; B.y = w0 * hb.y; B.z = w0 * hb.z; B.w = w0 * hb.w;

    int mx = deg;
    #pragma unroll
    for (int o = 16; o >= 1; o >>= 1)
        mx = max(mx, __shfl_xor_sync(0xffffffffu, mx, o));

    for (int i = 0; i < mx; i += 2) {
        bool v0 = i < deg, v1 = i + 1 < deg;
        int s0 = v0 ? g_csr[beg + i]     : vc;
        int s1 = v1 ? g_csr[beg + i + 1] : vc;
        float e0 = v0 ? __expf(lrelu(g_as[s0] + adv, 0.2f)) : 0.f;
        float e1 = v1 ? __expf(lrelu(g_as[s1] + adv, 0.2f)) : 0.f;
        float4 p0a = *reinterpret_cast<const float4*>(&g_h[s0 * D + ca]);
        float4 p0b = *reinterpret_cast<const float4*>(&g_h[s0 * D + cb]);
        float4 p1a = *reinterpret_cast<const float4*>(&g_h[s1 * D + ca]);
        float4 p1b = *reinterpret_cast<const float4*>(&g_h[s1 * D + cb]);
        denom += e0 + e1;
        A.x += e0 * p0a.x + e1 * p1a.x; A.y += e0 * p0a.y + e1 * p1a.y;
        A.z += e0 * p0a.z + e1 * p1a.z; A.w += e0 * p0a.w + e1 * p1a.w;
        B.x += e0 * p0b.x + e1 * p1b.x; B.y += e0 * p0b.y + e1 * p1b.y;
        B.z += e0 * p0b.z + e1 * p1b.z; B.w += e0 * p0b.w + e1 * p1b.w;
    }

    float inv = valid ? (1.0f / denom) : 0.f;
    float4 ba = *reinterpret_cast<const float4*>(&b[ca]);
    float4 bb = *reinterpret_cast<const float4*>(&b[cb]);
    float4 oa, ob;
    oa.x = lrelu(A.x * inv + ba.x, 0.01f); oa.y = lrelu(A.y * inv + ba.y, 0.01f);
    oa.z = lrelu(A.z * inv + ba.z, 0.01f); oa.w = lrelu(A.w * inv + ba.w, 0.01f);
    ob.x = lrelu(B.x * inv + bb.x, 0.01f); ob.y = lrelu(B.y * inv + bb.y, 0.01f);
    ob.z = lrelu(B.z * inv + bb.z, 0.01f); ob.w = lrelu(B.w * inv + bb.w, 0.01f);

    if (!last) {
        if (valid) {
            *reinterpret_cast<float4*>(&g_a[v * D + ca]) = oa;
            *reinterpret_cast<float4*>(&g_a[v * D + cb]) = ob;
        }
    } else {
        float4 wa = *reinterpret_cast<const float4*>(&Wout[ca]);
        float4 wb = *reinterpret_cast<const float4*>(&Wout[cb]);
        float s = oa.x * wa.x + oa.y * wa.y + oa.z * wa.z + oa.w * wa.w
                + ob.x * wb.x + ob.y * wb.y + ob.z * wb.z + ob.w * wb.w;
        #pragma unroll
        for (int o = 4; o >= 1; o >>= 1)
            s += __shfl_xor_sync(0xffffffffu, s, o);
        if (sl == 0 && valid) out[v] = s + bout[0];
    }
}

// ---------------- launch ----------------
extern "C" void kernel_launch(void* const* d_in, const int* in_sizes, int n_in,
                              void* d_out, int out_size) {
    const float* x = (const float*)d_in[0];
    const float* W[3]    = {(const float*)d_in[1], (const float*)d_in[5], (const float*)d_in[9]};
    const float* asrc[3] = {(const float*)d_in[2], (const float*)d_in[6], (const float*)d_in[10]};
    const float* adst[3] = {(const float*)d_in[3], (const float*)d_in[7], (const float*)d_in[11]};
    const float* bias[3] = {(const float*)d_in[4], (const float*)d_in[8], (const float*)d_in[12]};
    const float* Wout = (const float*)d_in[13];
    const float* bout = (const float*)d_in[14];
    const void*  eidx = d_in[15];

    int n = in_sizes[0] / D;
    int e = in_sizes[15] / 2;

    void* a_ptr = nullptr;
    cudaGetSymbolAddress(&a_ptr, g_a);
    const float* abuf = (const float*)a_ptr;

    cudaFuncSetAttribute(gemm_kernel,
                         cudaFuncAttributeMaxDynamicSharedMemorySize, GEMM_SMEM);

    int nb = (n + SCAN_B - 1) / SCAN_B;
    int eb = (e + 255) / 256;
    int zb = (n + 255) / 256;
    int gemm_b = (n + 127) / 128;
    int agg_b  = ((n + 3) / 4 * 32 + 255) / 256;

    init_kernel<<<zb, 256>>>(eidx, n);                                    // 1
    hist_kernel<<<eb, 256>>>(eidx, e);                                    // 2
    scan_block_kernel<<<nb, SCAN_B>>>(n);                                 // 3
    gemm_kernel<<<gemm_b, 256, GEMM_SMEM>>>(x, W[0], asrc[0], adst[0], n);// 4 <- profiled
    scan_fixup_kernel<<<nb, SCAN_B>>>(n, e, nb);                          // 5
    scatter_kernel<<<eb, 256>>>(eidx, e);                                 // 6
    agg_kernel<<<agg_b, 256>>>(bias[0], n, 0, Wout, bout, (float*)d_out); // 7

    for (int l = 1; l < 3; l++) {
        gemm_kernel<<<gemm_b, 256, GEMM_SMEM>>>(abuf, W[l], asrc[l], adst[l], n);
        agg_kernel<<<agg_b, 256>>>(bias[l], n, (l == 2) ? 1 : 0,
                                   Wout, bout, (float*)d_out);
    }
}

// round 7
// speedup vs baseline: 1.1782x; 1.0470x over previous
#include <cuda_runtime.h>
#include <cuda_fp16.h>

#define D 64
#define MAXN 50000
#define MAXE 800000
#define SCAN_B 1024
#define NB_MAX ((MAXN + SCAN_B - 1) / SCAN_B)

// ---------------- device scratch (no allocation allowed) ----------------
__device__ __align__(16) __half g_h[MAXN * D];   // fp16 feature payload
__device__ float g_a[MAXN * D];
__device__ float g_as[MAXN];
__device__ float g_ad[MAXN];
__device__ int   g_deg[MAXN];
__device__ int   g_cur[MAXN];
__device__ int   g_offs[MAXN + 1];
__device__ int   g_bsums[NB_MAX];
__device__ int   g_csr[MAXE];
__device__ int   g_is64;

__device__ __forceinline__ float lrelu(float x, float s) { return x > 0.f ? x : s * x; }

__device__ __forceinline__ int edge_val(const void* eidx, int idx, int is64) {
    return is64 ? (int)((const long long*)eidx)[idx] : ((const int*)eidx)[idx];
}

// ---------------- init / CSR build ----------------
__global__ void init_kernel(const void* eidx, int n) {
    int i = blockIdx.x * blockDim.x + threadIdx.x;
    if (i < n) { g_deg[i] = 0; g_cur[i] = 0; }
    if (i == 0) {
        const long long* p = (const long long*)eidx;
        int ok = 1;
        #pragma unroll
        for (int k = 0; k < 32; k++) {
            long long v = p[k];
            if (v < 0 || v >= (long long)n) { ok = 0; break; }
        }
        g_is64 = ok;
    }
}

__global__ void hist_kernel(const void* eidx, int e) {
    int i = blockIdx.x * blockDim.x + threadIdx.x;
    if (i < e) {
        int d = edge_val(eidx, e + i, g_is64);
        atomicAdd(&g_deg[d], 1);
    }
}

__global__ void scan_block_kernel(int n) {
    __shared__ int wsum[32];
    int t = threadIdx.x, lane = t & 31, wid = t >> 5;
    int gid = blockIdx.x * SCAN_B + t;
    int v = (gid < n) ? g_deg[gid] : 0;
    int x = v;
    #pragma unroll
    for (int o = 1; o < 32; o <<= 1) {
        int y = __shfl_up_sync(0xffffffffu, x, o);
        if (lane >= o) x += y;
    }
    if (lane == 31) wsum[wid] = x;
    __syncthreads();
    if (wid == 0) {
        int s = wsum[lane];
        #pragma unroll
        for (int o = 1; o < 32; o <<= 1) {
            int y = __shfl_up_sync(0xffffffffu, s, o);
            if (lane >= o) s += y;
        }
        wsum[lane] = s;
    }
    __syncthreads();
    int incl = x + (wid > 0 ? wsum[wid - 1] : 0);
    if (gid < n) g_offs[gid] = incl - v;
    if (t == SCAN_B - 1) g_bsums[blockIdx.x] = incl;
}

__global__ void scan_fixup_kernel(int n, int e, int nb) {
    __shared__ int s_pre;
    int t = threadIdx.x, b = blockIdx.x;
    if (t < 32) {
        int p = 0;
        for (int i = t; i < b; i += 32) p += g_bsums[i];
        #pragma unroll
        for (int o = 16; o >= 1; o >>= 1)
            p += __shfl_xor_sync(0xffffffffu, p, o);
        if (t == 0) s_pre = p;
    }
    __syncthreads();
    int pre = s_pre;
    int gid = b * SCAN_B + t;
    if (gid < n) g_offs[gid] += pre;
    if (gid == 0) g_offs[n] = e;
}

__global__ void scatter_kernel(const void* eidx, int e) {
    int i = blockIdx.x * blockDim.x + threadIdx.x;
    if (i < e) {
        int is64 = g_is64;
        int d = edge_val(eidx, e + i, is64);
        int s = edge_val(eidx, i, is64);
        int pos = g_offs[d] + atomicAdd(&g_cur[d], 1);
        g_csr[pos] = s;
    }
}

// ---------------- GEMM: H = X @ W^T, 128 rows/block, 8x4 per thread ------
#define XP 128
#define WP 68
#define SX_F (D * XP)
#define SW_F (D * WP)
#define GEMM_SMEM ((SX_F + SW_F + 2 * D) * 4)

__global__ void __launch_bounds__(256) gemm_kernel(
        const float* __restrict__ X, const float* __restrict__ W,
        const float* __restrict__ a_src, const float* __restrict__ a_dst, int n) {
    extern __shared__ __align__(16) float sm[];
    float* sXt   = sm;                 // [k*XP + r]
    float* sWt   = sm + SX_F;          // [k*WP + c]
    float* s_was = sm + SX_F + SW_F;
    float* s_wad = s_was + D;

    int t = threadIdx.x;
    int base = blockIdx.x * 128;

    {
        int c = t & 63, kh = (t >> 6) << 4;
        const float4* Wr = (const float4*)(W + c * D);
        #pragma unroll
        for (int q = 0; q < 4; q++) {
            int k0 = kh + q * 4;
            float4 w = Wr[k0 >> 2];
            sWt[(k0    ) * WP + c] = w.x;
            sWt[(k0 + 1) * WP + c] = w.y;
            sWt[(k0 + 2) * WP + c] = w.z;
            sWt[(k0 + 3) * WP + c] = w.w;
        }
    }
    {
        int r = t & 127, ch = (t >> 7) << 5;
        int gr = base + r;
        const float4* Xv = (const float4*)X;
        #pragma unroll
        for (int q = 0; q < 8; q++) {
            int c0 = ch + q * 4;
            float4 v = make_float4(0.f, 0.f, 0.f, 0.f);
            if (gr < n) v = Xv[gr * 16 + (c0 >> 2)];
            sXt[(c0    ) * XP + r] = v.x;
            sXt[(c0 + 1) * XP + r] = v.y;
            sXt[(c0 + 2) * XP + r] = v.z;
            sXt[(c0 + 3) * XP + r] = v.w;
        }
    }
    __syncthreads();

    if (t < D) {
        float was = 0.f, wad = 0.f;
        const float4* av = (const float4*)a_src;
        const float4* dv = (const float4*)a_dst;
        #pragma unroll
        for (int q = 0; q < 16; q++) {
            float4 wv = *reinterpret_cast<const float4*>(&sWt[t * WP + q * 4]);
            float4 a = av[q], dd = dv[q];
            was += wv.x * a.x + wv.y * a.y + wv.z * a.z + wv.w * a.w;
            wad += wv.x * dd.x + wv.y * dd.y + wv.z * dd.z + wv.w * dd.w;
        }
        s_was[t] = was; s_wad[t] = wad;
    }
    __syncthreads();

    if (t < 128) {
        int gr = base + t;
        if (gr < n) {
            float asp = 0.f, adp = 0.f;
            #pragma unroll 8
            for (int k = 0; k < D; k++) {
                float xv = sXt[k * XP + t];
                asp += xv * s_was[k];
                adp += xv * s_wad[k];
            }
            g_as[gr] = asp; g_ad[gr] = adp;
        }
    }

    int r0 = (t >> 4) << 3;
    int c0 = (t & 15) << 2;
    float acc[8][4];
    #pragma unroll
    for (int i = 0; i < 8; i++)
        #pragma unroll
        for (int j = 0; j < 4; j++) acc[i][j] = 0.f;

    #pragma unroll 4
    for (int k = 0; k < D; k++) {
        float4 xlo = *reinterpret_cast<const float4*>(&sXt[k * XP + r0]);
        float4 xhi = *reinterpret_cast<const float4*>(&sXt[k * XP + r0 + 4]);
        float4 wv  = *reinterpret_cast<const float4*>(&sWt[k * WP + c0]);
        acc[0][0] += xlo.x * wv.x; acc[0][1] += xlo.x * wv.y; acc[0][2] += xlo.x * wv.z; acc[0][3] += xlo.x * wv.w;
        acc[1][0] += xlo.y * wv.x; acc[1][1] += xlo.y * wv.y; acc[1][2] += xlo.y * wv.z; acc[1][3] += xlo.y * wv.w;
        acc[2][0] += xlo.z * wv.x; acc[2][1] += xlo.z * wv.y; acc[2][2] += xlo.z * wv.z; acc[2][3] += xlo.z * wv.w;
        acc[3][0] += xlo.w * wv.x; acc[3][1] += xlo.w * wv.y; acc[3][2] += xlo.w * wv.z; acc[3][3] += xlo.w * wv.w;
        acc[4][0] += xhi.x * wv.x; acc[4][1] += xhi.x * wv.y; acc[4][2] += xhi.x * wv.z; acc[4][3] += xhi.x * wv.w;
        acc[5][0] += xhi.y * wv.x; acc[5][1] += xhi.y * wv.y; acc[5][2] += xhi.y * wv.z; acc[5][3] += xhi.y * wv.w;
        acc[6][0] += xhi.z * wv.x; acc[6][1] += xhi.z * wv.y; acc[6][2] += xhi.z * wv.z; acc[6][3] += xhi.z * wv.w;
        acc[7][0] += xhi.w * wv.x; acc[7][1] += xhi.w * wv.y; acc[7][2] += xhi.w * wv.z; acc[7][3] += xhi.w * wv.w;
    }

    #pragma unroll
    for (int i = 0; i < 8; i++) {
        int gr = base + r0 + i;
        if (gr < n) {
            __half2 p0 = __floats2half2_rn(acc[i][0], acc[i][1]);
            __half2 p1 = __floats2half2_rn(acc[i][2], acc[i][3]);
            uint2 pk;
            pk.x = *reinterpret_cast<unsigned*>(&p0);
            pk.y = *reinterpret_cast<unsigned*>(&p1);
            *reinterpret_cast<uint2*>(&g_h[gr * D + c0]) = pk;
        }
    }
}

// ---------------- aggregation: 4 nodes/warp, 8 lanes/node, fp16 gathers ----
// lane sl owns 8 cols [sl*8, sl*8+8): one uint4 (16B) per edge per lane.
__global__ void agg_kernel(const float* __restrict__ b, int n, int last,
                           const float* __restrict__ Wout,
                           const float* __restrict__ bout,
                           float* __restrict__ out) {
    int wid_g = (blockIdx.x * blockDim.x + threadIdx.x) >> 5;
    int lane = threadIdx.x & 31;
    if (wid_g * 4 >= n) return;
    int sub = lane >> 3, sl = lane & 7;
    int v = wid_g * 4 + sub;
    bool valid = v < n;
    int vc = valid ? v : (n - 1);

    int beg = g_offs[vc];
    int deg = valid ? (g_offs[vc + 1] - beg) : 0;
    float adv = g_ad[vc];
    int c0 = sl * 8;

    float acc[8];
    float denom;
    {   // self-loop
        float w0 = valid ? __expf(lrelu(g_as[vc] + adv, 0.2f)) : 0.f;
        denom = w0;
        uint4 pk = *reinterpret_cast<const uint4*>(&g_h[vc * D + c0]);
        const __half2* hp = reinterpret_cast<const __half2*>(&pk);
        #pragma unroll
        for (int q = 0; q < 4; q++) {
            float2 f = __half22float2(hp[q]);
            acc[q * 2]     = w0 * f.x;
            acc[q * 2 + 1] = w0 * f.y;
        }
    }

    int mx = deg;
    #pragma unroll
    for (int o = 16; o >= 1; o >>= 1)
        mx = max(mx, __shfl_xor_sync(0xffffffffu, mx, o));

    for (int i = 0; i < mx; i += 2) {
        bool v0 = i < deg, v1 = i + 1 < deg;
        int s0 = v0 ? g_csr[beg + i]     : vc;
        int s1 = v1 ? g_csr[beg + i + 1] : vc;
        float e0 = v0 ? __expf(lrelu(g_as[s0] + adv, 0.2f)) : 0.f;
        float e1 = v1 ? __expf(lrelu(g_as[s1] + adv, 0.2f)) : 0.f;
        uint4 p0 = *reinterpret_cast<const uint4*>(&g_h[s0 * D + c0]);
        uint4 p1 = *reinterpret_cast<const uint4*>(&g_h[s1 * D + c0]);
        const __half2* h0 = reinterpret_cast<const __half2*>(&p0);
        const __half2* h1 = reinterpret_cast<const __half2*>(&p1);
        denom += e0 + e1;
        #pragma unroll
        for (int q = 0; q < 4; q++) {
            float2 f0 = __half22float2(h0[q]);
            float2 f1 = __half22float2(h1[q]);
            acc[q * 2]     += e0 * f0.x + e1 * f1.x;
            acc[q * 2 + 1] += e0 * f0.y + e1 * f1.y;
        }
    }

    float inv = valid ? (1.0f / denom) : 0.f;
    float o8[8];
    #pragma unroll
    for (int q = 0; q < 8; q++)
        o8[q] = lrelu(acc[q] * inv + b[c0 + q], 0.01f);

    if (!last) {
        if (valid) {
            float4 va; va.x = o8[0]; va.y = o8[1]; va.z = o8[2]; va.w = o8[3];
            float4 vb; vb.x = o8[4]; vb.y = o8[5]; vb.z = o8[6]; vb.w = o8[7];
            *reinterpret_cast<float4*>(&g_a[v * D + c0])     = va;
            *reinterpret_cast<float4*>(&g_a[v * D + c0 + 4]) = vb;
        }
    } else {
        float s = 0.f;
        #pragma unroll
        for (int q = 0; q < 8; q++) s += o8[q] * Wout[c0 + q];
        #pragma unroll
        for (int o = 4; o >= 1; o >>= 1)
            s += __shfl_xor_sync(0xffffffffu, s, o);
        if (sl == 0 && valid) out[v] = s + bout[0];
    }
}

// ---------------- launch ----------------
extern "C" void kernel_launch(void* const* d_in, const int* in_sizes, int n_in,
                              void* d_out, int out_size) {
    const float* x = (const float*)d_in[0];
    const float* W[3]    = {(const float*)d_in[1], (const float*)d_in[5], (const float*)d_in[9]};
    const float* asrc[3] = {(const float*)d_in[2], (const float*)d_in[6], (const float*)d_in[10]};
    const float* adst[3] = {(const float*)d_in[3], (const float*)d_in[7], (const float*)d_in[11]};
    const float* bias[3] = {(const float*)d_in[4], (const float*)d_in[8], (const float*)d_in[12]};
    const float* Wout = (const float*)d_in[13];
    const float* bout = (const float*)d_in[14];
    const void*  eidx = d_in[15];

    int n = in_sizes[0] / D;
    int e = in_sizes[15] / 2;

    void* a_ptr = nullptr;
    cudaGetSymbolAddress(&a_ptr, g_a);
    const float* abuf = (const float*)a_ptr;

    cudaFuncSetAttribute(gemm_kernel,
                         cudaFuncAttributeMaxDynamicSharedMemorySize, GEMM_SMEM);

    int nb = (n + SCAN_B - 1) / SCAN_B;
    int eb = (e + 255) / 256;
    int zb = (n + 255) / 256;
    int gemm_b = (n + 127) / 128;
    int agg_b  = ((n + 3) / 4 * 32 + 255) / 256;

    init_kernel<<<zb, 256>>>(eidx, n);
    hist_kernel<<<eb, 256>>>(eidx, e);
    scan_block_kernel<<<nb, SCAN_B>>>(n);
    gemm_kernel<<<gemm_b, 256, GEMM_SMEM>>>(x, W[0], asrc[0], adst[0], n);  // profiled
    scan_fixup_kernel<<<nb, SCAN_B>>>(n, e, nb);
    scatter_kernel<<<eb, 256>>>(eidx, e);
    agg_kernel<<<agg_b, 256>>>(bias[0], n, 0, Wout, bout, (float*)d_out);

    for (int l = 1; l < 3; l++) {
        gemm_kernel<<<gemm_b, 256, GEMM_SMEM>>>(abuf, W[l], asrc[l], adst[l], n);
        agg_kernel<<<agg_b, 256>>>(bias[l], n, (l == 2) ? 1 : 0,
                                   Wout, bout, (float*)d_out);
    }
}

// round 8
// speedup vs baseline: 1.4342x; 1.2172x over previous
#include <cuda_runtime.h>
#include <cuda_fp16.h>

#define D 64
#define MAXN 50000
#define MAXE 800000
#define SCAN_B 1024
#define NB_MAX ((MAXN + SCAN_B - 1) / SCAN_B)

// ---------------- device scratch (no allocation allowed) ----------------
__device__ __align__(16) __half g_h[MAXN * D];   // fp16 feature payload
__device__ float g_a[MAXN * D];
__device__ float g_as[MAXN];
__device__ float g_ad[MAXN];
__device__ int   g_deg[MAXN];
__device__ int   g_cur[MAXN];
__device__ int   g_offs[MAXN + 1];
__device__ int   g_bsums[NB_MAX];
__device__ int   g_csr[MAXE];
__device__ int   g_is64;

__device__ __forceinline__ float lrelu(float x, float s) { return x > 0.f ? x : s * x; }

__device__ __forceinline__ int edge_val(const void* eidx, int idx, int is64) {
    return is64 ? (int)((const long long*)eidx)[idx] : ((const int*)eidx)[idx];
}

__device__ __forceinline__ unsigned f2tf32(float f) {
    unsigned u;
    asm("cvt.rna.tf32.f32 %0, %1;" : "=r"(u) : "f"(f));
    return u;
}

// ---------------- init / CSR build ----------------
__global__ void init_kernel(const void* eidx, int n) {
    int i = blockIdx.x * blockDim.x + threadIdx.x;
    if (i < n) { g_deg[i] = 0; g_cur[i] = 0; }
    if (i == 0) {
        const long long* p = (const long long*)eidx;
        int ok = 1;
        #pragma unroll
        for (int k = 0; k < 32; k++) {
            long long v = p[k];
            if (v < 0 || v >= (long long)n) { ok = 0; break; }
        }
        g_is64 = ok;
    }
}

__global__ void hist_kernel(const void* eidx, int e) {
    int i = blockIdx.x * blockDim.x + threadIdx.x;
    if (i < e) {
        int d = edge_val(eidx, e + i, g_is64);
        atomicAdd(&g_deg[d], 1);
    }
}

__global__ void scan_block_kernel(int n) {
    __shared__ int wsum[32];
    int t = threadIdx.x, lane = t & 31, wid = t >> 5;
    int gid = blockIdx.x * SCAN_B + t;
    int v = (gid < n) ? g_deg[gid] : 0;
    int x = v;
    #pragma unroll
    for (int o = 1; o < 32; o <<= 1) {
        int y = __shfl_up_sync(0xffffffffu, x, o);
        if (lane >= o) x += y;
    }
    if (lane == 31) wsum[wid] = x;
    __syncthreads();
    if (wid == 0) {
        int s = wsum[lane];
        #pragma unroll
        for (int o = 1; o < 32; o <<= 1) {
            int y = __shfl_up_sync(0xffffffffu, s, o);
            if (lane >= o) s += y;
        }
        wsum[lane] = s;
    }
    __syncthreads();
    int incl = x + (wid > 0 ? wsum[wid - 1] : 0);
    if (gid < n) g_offs[gid] = incl - v;
    if (t == SCAN_B - 1) g_bsums[blockIdx.x] = incl;
}

__global__ void scan_fixup_kernel(int n, int e, int nb) {
    __shared__ int s_pre;
    int t = threadIdx.x, b = blockIdx.x;
    if (t < 32) {
        int p = 0;
        for (int i = t; i < b; i += 32) p += g_bsums[i];
        #pragma unroll
        for (int o = 16; o >= 1; o >>= 1)
            p += __shfl_xor_sync(0xffffffffu, p, o);
        if (t == 0) s_pre = p;
    }
    __syncthreads();
    int pre = s_pre;
    int gid = b * SCAN_B + t;
    if (gid < n) g_offs[gid] += pre;
    if (gid == 0) g_offs[n] = e;
}

__global__ void scatter_kernel(const void* eidx, int e) {
    int i = blockIdx.x * blockDim.x + threadIdx.x;
    if (i < e) {
        int is64 = g_is64;
        int d = edge_val(eidx, e + i, is64);
        int s = edge_val(eidx, i, is64);
        int pos = g_offs[d] + atomicAdd(&g_cur[d], 1);
        g_csr[pos] = s;
    }
}

// ---------------- GEMM: H = X @ W^T via tf32 mma.sync ----------------
// 256 threads = 8 warps, 128 rows/block; warp = 16 rows x 64 cols
// (8 n-tiles of m16n8k8, 8 k-steps). X,W staged natural row-major, pitch 68
// -> all fragment LDS.32 are bank-conflict-free. Logits from C fragments.
#define XP 68
#define SX_F (128 * XP)
#define SW_F (D * XP)
#define GEMM_SMEM ((SX_F + SW_F) * 4)   // 52224 bytes

__global__ void __launch_bounds__(256) gemm_kernel(
        const float* __restrict__ X, const float* __restrict__ W,
        const float* __restrict__ a_src, const float* __restrict__ a_dst, int n) {
    extern __shared__ __align__(16) float sm[];
    float* sX = sm;            // [r][k], pitch XP
    float* sW = sm + SX_F;     // [c][k], pitch XP

    int t = threadIdx.x;
    int base = blockIdx.x * 128;

    // stage X natural (coalesced float4 -> STS.128)
    {
        const float4* Xv = (const float4*)X;
        #pragma unroll
        for (int idx = t; idx < 128 * 16; idx += 256) {
            int r = idx >> 4, q = idx & 15;
            int gr = base + r;
            float4 v = make_float4(0.f, 0.f, 0.f, 0.f);
            if (gr < n) v = Xv[gr * 16 + q];
            *reinterpret_cast<float4*>(&sX[r * XP + q * 4]) = v;
        }
    }
    // stage W natural
    {
        const float4* Wv = (const float4*)W;
        #pragma unroll
        for (int idx = t; idx < 64 * 16; idx += 256) {
            int c = idx >> 4, q = idx & 15;
            *reinterpret_cast<float4*>(&sW[c * XP + q * 4]) = Wv[idx];
        }
    }
    __syncthreads();

    int lane = t & 31;
    int wr   = (t >> 5) << 4;      // warp row base (0..112)
    int gid  = lane >> 2;          // 0..7
    int tig  = lane & 3;           // 0..3

    float c[8][4];
    #pragma unroll
    for (int nt = 0; nt < 8; nt++)
        #pragma unroll
        for (int j = 0; j < 4; j++) c[nt][j] = 0.f;

    const float* arow0 = &sX[(wr + gid) * XP + tig];       // row wr+gid
    const float* arow1 = arow0 + 8 * XP;                   // row wr+gid+8
    const float* brow  = &sW[gid * XP + tig];              // col n0+gid

    #pragma unroll
    for (int ks = 0; ks < 8; ks++) {
        int k0 = ks * 8;
        unsigned a0 = f2tf32(arow0[k0]);
        unsigned a1 = f2tf32(arow1[k0]);
        unsigned a2 = f2tf32(arow0[k0 + 4]);
        unsigned a3 = f2tf32(arow1[k0 + 4]);
        #pragma unroll
        for (int nt = 0; nt < 8; nt++) {
            unsigned b0 = f2tf32(brow[nt * 8 * XP + k0]);
            unsigned b1 = f2tf32(brow[nt * 8 * XP + k0 + 4]);
            asm volatile(
                "mma.sync.aligned.m16n8k8.row.col.f32.tf32.tf32.f32 "
                "{%0,%1,%2,%3}, {%4,%5,%6,%7}, {%8,%9}, {%0,%1,%2,%3};"
                : "+f"(c[nt][0]), "+f"(c[nt][1]), "+f"(c[nt][2]), "+f"(c[nt][3])
                : "r"(a0), "r"(a1), "r"(a2), "r"(a3), "r"(b0), "r"(b1));
        }
    }

    // epilogue: logits from C fragments + fp16 payload store
    int gr0 = base + wr + gid;       // row of c[*][0..1]
    int gr1 = gr0 + 8;               // row of c[*][2..3]
    float asp0 = 0.f, adp0 = 0.f, asp1 = 0.f, adp1 = 0.f;
    #pragma unroll
    for (int nt = 0; nt < 8; nt++) {
        int col = nt * 8 + tig * 2;
        float sa0 = a_src[col], sa1 = a_src[col + 1];
        float da0 = a_dst[col], da1 = a_dst[col + 1];
        asp0 += c[nt][0] * sa0 + c[nt][1] * sa1;
        adp0 += c[nt][0] * da0 + c[nt][1] * da1;
        asp1 += c[nt][2] * sa0 + c[nt][3] * sa1;
        adp1 += c[nt][2] * da0 + c[nt][3] * da1;

        __half2 h01 = __floats2half2_rn(c[nt][0], c[nt][1]);
        __half2 h23 = __floats2half2_rn(c[nt][2], c[nt][3]);
        if (gr0 < n) *reinterpret_cast<__half2*>(&g_h[gr0 * D + col]) = h01;
        if (gr1 < n) *reinterpret_cast<__half2*>(&g_h[gr1 * D + col]) = h23;
    }
    // reduce over the 4 lanes of the group (tig)
    #pragma unroll
    for (int o = 1; o <= 2; o <<= 1) {
        asp0 += __shfl_xor_sync(0xffffffffu, asp0, o);
        adp0 += __shfl_xor_sync(0xffffffffu, adp0, o);
        asp1 += __shfl_xor_sync(0xffffffffu, asp1, o);
        adp1 += __shfl_xor_sync(0xffffffffu, adp1, o);
    }
    if (tig == 0) {
        if (gr0 < n) { g_as[gr0] = asp0; g_ad[gr0] = adp0; }
        if (gr1 < n) { g_as[gr1] = asp1; g_ad[gr1] = adp1; }
    }
}

// ---------------- aggregation: 4 nodes/warp, 8 lanes/node, fp16 gathers ----
__global__ void agg_kernel(const float* __restrict__ b, int n, int last,
                           const float* __restrict__ Wout,
                           const float* __restrict__ bout,
                           float* __restrict__ out) {
    int wid_g = (blockIdx.x * blockDim.x + threadIdx.x) >> 5;
    int lane = threadIdx.x & 31;
    if (wid_g * 4 >= n) return;
    int sub = lane >> 3, sl = lane & 7;
    int v = wid_g * 4 + sub;
    bool valid = v < n;
    int vc = valid ? v : (n - 1);

    int beg = g_offs[vc];
    int deg = valid ? (g_offs[vc + 1] - beg) : 0;
    float adv = g_ad[vc];
    int c0 = sl * 8;

    float acc[8];
    float denom;
    {
        float w0 = valid ? __expf(lrelu(g_as[vc] + adv, 0.2f)) : 0.f;
        denom = w0;
        uint4 pk = *reinterpret_cast<const uint4*>(&g_h[vc * D + c0]);
        const __half2* hp = reinterpret_cast<const __half2*>(&pk);
        #pragma unroll
        for (int q = 0; q < 4; q++) {
            float2 f = __half22float2(hp[q]);
            acc[q * 2]     = w0 * f.x;
            acc[q * 2 + 1] = w0 * f.y;
        }
    }

    int mx = deg;
    #pragma unroll
    for (int o = 16; o >= 1; o >>= 1)
        mx = max(mx, __shfl_xor_sync(0xffffffffu, mx, o));

    for (int i = 0; i < mx; i += 2) {
        bool v0 = i < deg, v1 = i + 1 < deg;
        int s0 = v0 ? g_csr[beg + i]     : vc;
        int s1 = v1 ? g_csr[beg + i + 1] : vc;
        float e0 = v0 ? __expf(lrelu(g_as[s0] + adv, 0.2f)) : 0.f;
        float e1 = v1 ? __expf(lrelu(g_as[s1] + adv, 0.2f)) : 0.f;
        uint4 p0 = *reinterpret_cast<const uint4*>(&g_h[s0 * D + c0]);
        uint4 p1 = *reinterpret_cast<const uint4*>(&g_h[s1 * D + c0]);
        const __half2* h0 = reinterpret_cast<const __half2*>(&p0);
        const __half2* h1 = reinterpret_cast<const __half2*>(&p1);
        denom += e0 + e1;
        #pragma unroll
        for (int q = 0; q < 4; q++) {
            float2 f0 = __half22float2(h0[q]);
            float2 f1 = __half22float2(h1[q]);
            acc[q * 2]     += e0 * f0.x + e1 * f1.x;
            acc[q * 2 + 1] += e0 * f0.y + e1 * f1.y;
        }
    }

    float inv = valid ? (1.0f / denom) : 0.f;
    float o8[8];
    #pragma unroll
    for (int q = 0; q < 8; q++)
        o8[q] = lrelu(acc[q] * inv + b[c0 + q], 0.01f);

    if (!last) {
        if (valid) {
            float4 va; va.x = o8[0]; va.y = o8[1]; va.z = o8[2]; va.w = o8[3];
            float4 vb; vb.x = o8[4]; vb.y = o8[5]; vb.z = o8[6]; vb.w = o8[7];
            *reinterpret_cast<float4*>(&g_a[v * D + c0])     = va;
            *reinterpret_cast<float4*>(&g_a[v * D + c0 + 4]) = vb;
        }
    } else {
        float s = 0.f;
        #pragma unroll
        for (int q = 0; q < 8; q++) s += o8[q] * Wout[c0 + q];
        #pragma unroll
        for (int o = 4; o >= 1; o >>= 1)
            s += __shfl_xor_sync(0xffffffffu, s, o);
        if (sl == 0 && valid) out[v] = s + bout[0];
    }
}

// ---------------- launch ----------------
extern "C" void kernel_launch(void* const* d_in, const int* in_sizes, int n_in,
                              void* d_out, int out_size) {
    const float* x = (const float*)d_in[0];
    const float* W[3]    = {(const float*)d_in[1], (const float*)d_in[5], (const float*)d_in[9]};
    const float* asrc[3] = {(const float*)d_in[2], (const float*)d_in[6], (const float*)d_in[10]};
    const float* adst[3] = {(const float*)d_in[3], (const float*)d_in[7], (const float*)d_in[11]};
    const float* bias[3] = {(const float*)d_in[4], (const float*)d_in[8], (const float*)d_in[12]};
    const float* Wout = (const float*)d_in[13];
    const float* bout = (const float*)d_in[14];
    const void*  eidx = d_in[15];

    int n = in_sizes[0] / D;
    int e = in_sizes[15] / 2;

    void* a_ptr = nullptr;
    cudaGetSymbolAddress(&a_ptr, g_a);
    const float* abuf = (const float*)a_ptr;

    cudaFuncSetAttribute(gemm_kernel,
                         cudaFuncAttributeMaxDynamicSharedMemorySize, GEMM_SMEM);

    int nb = (n + SCAN_B - 1) / SCAN_B;
    int eb = (e + 255) / 256;
    int zb = (n + 255) / 256;
    int gemm_b = (n + 127) / 128;
    int agg_b  = ((n + 3) / 4 * 32 + 255) / 256;

    init_kernel<<<zb, 256>>>(eidx, n);
    hist_kernel<<<eb, 256>>>(eidx, e);
    scan_block_kernel<<<nb, SCAN_B>>>(n);
    gemm_kernel<<<gemm_b, 256, GEMM_SMEM>>>(x, W[0], asrc[0], adst[0], n);  // profiled
    scan_fixup_kernel<<<nb, SCAN_B>>>(n, e, nb);
    scatter_kernel<<<eb, 256>>>(eidx, e);
    agg_kernel<<<agg_b, 256>>>(bias[0], n, 0, Wout, bout, (float*)d_out);

    for (int l = 1; l < 3; l++) {
        gemm_kernel<<<gemm_b, 256, GEMM_SMEM>>>(abuf, W[l], asrc[l], adst[l], n);
        agg_kernel<<<agg_b, 256>>>(bias[l], n, (l == 2) ? 1 : 0,
                                   Wout, bout, (float*)d_out);
    }
}